// round 13
// baseline (speedup 1.0000x reference)
#include <cuda_runtime.h>
#include <cuda_bf16.h>
#include <math.h>

// Problem constants
#define Bc    2
#define Vc    4
#define Jc    24
#define HMc   96
#define VOLD  48
#define VOXN  (VOLD*VOLD*VOLD)      // 110592 voxels per batch
#define TPB   128                   // threads per block (main kernel)
#define UPT   6                     // voxels per thread
#define NBLK  (VOXN/(TPB*UPT))      // 144 blocks per batch

// Transposed heatmaps: [b, v, h, w, j] with j contiguous (24 floats = 6 float4).
__device__ float4 g_hmT4[Bc*Vc*HMc*HMc*(Jc/4)];
// Per-block partial sums: [b*NBLK + blk][j] = (sum_e, sum_e*cx, sum_e*cy, sum_e*cz)
__device__ float4 g_partial[Bc*NBLK*Jc];

// ---------------------------------------------------------------------------
// Kernel A: transpose heatmaps [b,v,j,h,w] -> [b,v,h,w,j]
// One block per (b,v,h); smem tile avoids uncoalesced global access.
// ---------------------------------------------------------------------------
__global__ void transpose_kernel(const float* __restrict__ hm) {
    __shared__ float s[Jc][33];
    const int bid = blockIdx.x;            // 0 .. B*V*HM-1
    const int h   = bid % HMc;
    const int bv  = bid / HMc;
    const int tx  = threadIdx.x;           // 0..31 (w within chunk)
    const int ty  = threadIdx.y;           // 0..23 (j)
    const int t   = ty * 32 + tx;          // 0..767
    float* out = (float*)g_hmT4;

    #pragma unroll
    for (int wc = 0; wc < 3; ++wc) {
        // coalesced read along w for each j row
        s[ty][tx] = hm[((size_t)(bv*Jc + ty)*HMc + h)*HMc + wc*32 + tx];
        __syncthreads();
        // coalesced write along j-fastest layout
        const int j = t % Jc;
        const int w = t / Jc;               // 0..31
        out[(((size_t)bv*HMc + h)*HMc + wc*32 + w)*Jc + j] = s[j][w];
        __syncthreads();
    }
}

// ---------------------------------------------------------------------------
// Kernel B: main fused kernel.
// Each thread processes UPT voxels: project into 4 views, bilinear-gather
// 24 joints (vectorized float4 loads from transposed heatmaps), exp, and
// accumulate (e, e*cx, e*cy, e*cz) per joint. Block-level deterministic
// reduction -> g_partial.
// ---------------------------------------------------------------------------
__device__ __forceinline__ void corner_acc(const float4* __restrict__ plane,
                                           int y, int x, float w, float4* vol) {
    if (w > 0.0f) {
        const float4* p = plane + ((y * HMc + x) * (Jc/4));
        #pragma unroll
        for (int q = 0; q < 6; ++q) {
            float4 f = p[q];
            vol[q].x += w * f.x;
            vol[q].y += w * f.y;
            vol[q].z += w * f.z;
            vol[q].w += w * f.w;
        }
    }
}

__global__ void __launch_bounds__(TPB) main_kernel(const float* __restrict__ proj,
                                                   const float* __restrict__ coords) {
    __shared__ float P[Vc*12];
    __shared__ float4 s4[TPB/32][Jc];

    const int b   = blockIdx.y;
    const int tid = threadIdx.x;
    if (tid < Vc*12) P[tid] = proj[b*Vc*12 + tid];
    __syncthreads();

    float4 acc[Jc];
    #pragma unroll
    for (int j = 0; j < Jc; ++j) acc[j] = make_float4(0.f, 0.f, 0.f, 0.f);

    const int base_n = blockIdx.x * (TPB*UPT);
    const float*  cv = coords + (size_t)b * VOXN * 3;
    const float4* hb = g_hmT4 + (size_t)b * (Vc*HMc*HMc*(Jc/4));

    #pragma unroll 1
    for (int u = 0; u < UPT; ++u) {
        const int n = base_n + u*TPB + tid;
        const float cx = cv[n*3 + 0];
        const float cy = cv[n*3 + 1];
        const float cz = cv[n*3 + 2];

        float4 vol[6];
        #pragma unroll
        for (int q = 0; q < 6; ++q) vol[q] = make_float4(0.f, 0.f, 0.f, 0.f);

        #pragma unroll
        for (int v = 0; v < Vc; ++v) {
            const float* M = P + v*12;
            const float zc = M[8]*cx + M[9]*cy + M[10]*cz + M[11];
            if (zc > 0.0f) {
                const float inv = __fdividef(1.0f, zc);
                const float px = (M[0]*cx + M[1]*cy + M[2]*cz + M[3]) * inv;
                const float py = (M[4]*cx + M[5]*cy + M[6]*cz + M[7]) * inv;
                // ix = px * (W-1)/W, iy = py * (H-1)/H (H == W == 96)
                const float ix = px * (95.0f/96.0f);
                const float iy = py * (95.0f/96.0f);
                const float fx = floorf(ix), fy = floorf(iy);
                const float wx1 = ix - fx, wy1 = iy - fy;
                const float wx0 = 1.0f - wx1, wy0 = 1.0f - wy1;
                const int x0 = (int)fx, y0 = (int)fy;
                const bool vx0 = (unsigned)x0       < (unsigned)HMc;
                const bool vx1 = (unsigned)(x0 + 1) < (unsigned)HMc;
                const bool vy0 = (unsigned)y0       < (unsigned)HMc;
                const bool vy1 = (unsigned)(y0 + 1) < (unsigned)HMc;
                const float w00 = (vy0 && vx0) ? wy0*wx0 : 0.0f;
                const float w01 = (vy0 && vx1) ? wy0*wx1 : 0.0f;
                const float w10 = (vy1 && vx0) ? wy1*wx0 : 0.0f;
                const float w11 = (vy1 && vx1) ? wy1*wx1 : 0.0f;
                const float4* plane = hb + (size_t)v * (HMc*HMc*(Jc/4));
                corner_acc(plane, y0,   x0,   w00, vol);
                corner_acc(plane, y0,   x0+1, w01, vol);
                corner_acc(plane, y0+1, x0,   w10, vol);
                corner_acc(plane, y0+1, x0+1, w11, vol);
            }
        }

        // exp (volume in [0, 4] -> no max-shift needed) and accumulate
        #pragma unroll
        for (int q = 0; q < 6; ++q) {
            float e;
            e = __expf(vol[q].x);
            acc[q*4+0].x += e; acc[q*4+0].y += e*cx; acc[q*4+0].z += e*cy; acc[q*4+0].w += e*cz;
            e = __expf(vol[q].y);
            acc[q*4+1].x += e; acc[q*4+1].y += e*cx; acc[q*4+1].z += e*cy; acc[q*4+1].w += e*cz;
            e = __expf(vol[q].z);
            acc[q*4+2].x += e; acc[q*4+2].y += e*cx; acc[q*4+2].z += e*cy; acc[q*4+2].w += e*cz;
            e = __expf(vol[q].w);
            acc[q*4+3].x += e; acc[q*4+3].y += e*cx; acc[q*4+3].z += e*cy; acc[q*4+3].w += e*cz;
        }
    }

    // warp reduction (deterministic), then cross-warp via smem
    const int lane = tid & 31;
    const int wrp  = tid >> 5;
    #pragma unroll
    for (int j = 0; j < Jc; ++j) {
        float4 a = acc[j];
        #pragma unroll
        for (int o = 16; o > 0; o >>= 1) {
            a.x += __shfl_xor_sync(0xffffffffu, a.x, o);
            a.y += __shfl_xor_sync(0xffffffffu, a.y, o);
            a.z += __shfl_xor_sync(0xffffffffu, a.z, o);
            a.w += __shfl_xor_sync(0xffffffffu, a.w, o);
        }
        if (lane == 0) s4[wrp][j] = a;
    }
    __syncthreads();
    if (tid < Jc) {
        float4 a = s4[0][tid], b2 = s4[1][tid], c2 = s4[2][tid], d2 = s4[3][tid];
        float4 r = make_float4(a.x + b2.x + c2.x + d2.x,
                               a.y + b2.y + c2.y + d2.y,
                               a.z + b2.z + c2.z + d2.z,
                               a.w + b2.w + c2.w + d2.w);
        g_partial[(b*NBLK + blockIdx.x)*Jc + tid] = r;
    }
}

// ---------------------------------------------------------------------------
// Kernel C: reduce per-block partials -> coordinates [B, J, 3]
// One block per (b, j).
// ---------------------------------------------------------------------------
__global__ void finalize_kernel(float* __restrict__ out) {
    const int bj = blockIdx.x;            // 0..47
    const int b  = bj / Jc;
    const int j  = bj % Jc;
    const int tid = threadIdx.x;          // 128

    float4 a = make_float4(0.f, 0.f, 0.f, 0.f);
    for (int blk = tid; blk < NBLK; blk += 128) {
        float4 p = g_partial[(b*NBLK + blk)*Jc + j];
        a.x += p.x; a.y += p.y; a.z += p.z; a.w += p.w;
    }
    #pragma unroll
    for (int o = 16; o > 0; o >>= 1) {
        a.x += __shfl_xor_sync(0xffffffffu, a.x, o);
        a.y += __shfl_xor_sync(0xffffffffu, a.y, o);
        a.z += __shfl_xor_sync(0xffffffffu, a.z, o);
        a.w += __shfl_xor_sync(0xffffffffu, a.w, o);
    }
    __shared__ float4 s[4];
    const int lane = tid & 31, wrp = tid >> 5;
    if (lane == 0) s[wrp] = a;
    __syncthreads();
    if (tid == 0) {
        float4 r = s[0];
        r.x += s[1].x + s[2].x + s[3].x;
        r.y += s[1].y + s[2].y + s[3].y;
        r.z += s[1].z + s[2].z + s[3].z;
        r.w += s[1].w + s[2].w + s[3].w;
        const float inv = 1.0f / r.x;
        out[bj*3 + 0] = r.y * inv;
        out[bj*3 + 1] = r.z * inv;
        out[bj*3 + 2] = r.w * inv;
    }
}

// ---------------------------------------------------------------------------
extern "C" void kernel_launch(void* const* d_in, const int* in_sizes, int n_in,
                              void* d_out, int out_size) {
    const float* heatmaps = (const float*)d_in[0];   // (2,4,24,96,96)
    const float* proj     = (const float*)d_in[1];   // (2,4,3,4)
    const float* coords   = (const float*)d_in[2];   // (2,48,48,48,3)
    float* out = (float*)d_out;                      // (2,24,3)

    transpose_kernel<<<Bc*Vc*HMc, dim3(32, Jc)>>>(heatmaps);
    dim3 grid(NBLK, Bc);
    main_kernel<<<grid, TPB>>>(proj, coords);
    finalize_kernel<<<Bc*Jc, 128>>>(out);
}

// round 14
// speedup vs baseline: 1.0195x; 1.0195x over previous
#include <cuda_runtime.h>
#include <cuda_bf16.h>
#include <math.h>

// Problem constants
#define Bc    2
#define Vc    4
#define Jc    24
#define HMc   96
#define VOLD  48
#define VOXN  (VOLD*VOLD*VOLD)      // 110592 voxels per batch
#define TPB   128                   // threads per block (main kernel)
#define UPT   6                     // voxels per thread
#define NBLK  (VOXN/(TPB*UPT))      // 144 blocks per batch

// Transposed heatmaps: [b, v, h, w, j] with j contiguous (24 floats = 6 float4).
__device__ float4 g_hmT4[Bc*Vc*HMc*HMc*(Jc/4)];
// Per-block partial sums: [b*NBLK + blk][j] = (sum_e, sum_e*cx, sum_e*cy, sum_e*cz)
__device__ float4 g_partial[Bc*NBLK*Jc];

// ---------------------------------------------------------------------------
// Kernel A: transpose heatmaps [b,v,j,h,w] -> [b,v,h,w,j]
// One block per (b,v,h); smem tile avoids uncoalesced global access.
// ---------------------------------------------------------------------------
__global__ void transpose_kernel(const float* __restrict__ hm) {
    __shared__ float s[Jc][33];
    const int bid = blockIdx.x;            // 0 .. B*V*HM-1
    const int h   = bid % HMc;
    const int bv  = bid / HMc;
    const int tx  = threadIdx.x;           // 0..31 (w within chunk)
    const int ty  = threadIdx.y;           // 0..23 (j)
    const int t   = ty * 32 + tx;          // 0..767
    float* out = (float*)g_hmT4;

    #pragma unroll
    for (int wc = 0; wc < 3; ++wc) {
        // coalesced read along w for each j row
        s[ty][tx] = hm[((size_t)(bv*Jc + ty)*HMc + h)*HMc + wc*32 + tx];
        __syncthreads();
        // coalesced write along j-fastest layout
        const int j = t % Jc;
        const int w = t / Jc;               // 0..31
        out[(((size_t)bv*HMc + h)*HMc + wc*32 + w)*Jc + j] = s[j][w];
        __syncthreads();
    }
}

// ---------------------------------------------------------------------------
// Kernel B: main fused kernel.
// Each thread processes UPT voxels: project into 4 views, bilinear-gather
// 24 joints (vectorized float4 loads from transposed heatmaps), exp, and
// accumulate (e, e*cx, e*cy, e*cz) per joint. Block-level deterministic
// reduction -> g_partial.
// ---------------------------------------------------------------------------
__device__ __forceinline__ void corner_acc(const float4* __restrict__ plane,
                                           int y, int x, float w, float4* vol) {
    if (w > 0.0f) {
        const float4* p = plane + ((y * HMc + x) * (Jc/4));
        #pragma unroll
        for (int q = 0; q < 6; ++q) {
            float4 f = p[q];
            vol[q].x += w * f.x;
            vol[q].y += w * f.y;
            vol[q].z += w * f.z;
            vol[q].w += w * f.w;
        }
    }
}

__global__ void __launch_bounds__(TPB) main_kernel(const float* __restrict__ proj,
                                                   const float* __restrict__ coords) {
    __shared__ float P[Vc*12];
    __shared__ float4 s4[TPB/32][Jc];

    const int b   = blockIdx.y;
    const int tid = threadIdx.x;
    if (tid < Vc*12) P[tid] = proj[b*Vc*12 + tid];
    __syncthreads();

    float4 acc[Jc];
    #pragma unroll
    for (int j = 0; j < Jc; ++j) acc[j] = make_float4(0.f, 0.f, 0.f, 0.f);

    const int base_n = blockIdx.x * (TPB*UPT);
    const float*  cv = coords + (size_t)b * VOXN * 3;
    const float4* hb = g_hmT4 + (size_t)b * (Vc*HMc*HMc*(Jc/4));

    #pragma unroll 1
    for (int u = 0; u < UPT; ++u) {
        const int n = base_n + u*TPB + tid;
        const float cx = cv[n*3 + 0];
        const float cy = cv[n*3 + 1];
        const float cz = cv[n*3 + 2];

        float4 vol[6];
        #pragma unroll
        for (int q = 0; q < 6; ++q) vol[q] = make_float4(0.f, 0.f, 0.f, 0.f);

        #pragma unroll
        for (int v = 0; v < Vc; ++v) {
            const float* M = P + v*12;
            const float zc = M[8]*cx + M[9]*cy + M[10]*cz + M[11];
            if (zc > 0.0f) {
                const float inv = __fdividef(1.0f, zc);
                const float px = (M[0]*cx + M[1]*cy + M[2]*cz + M[3]) * inv;
                const float py = (M[4]*cx + M[5]*cy + M[6]*cz + M[7]) * inv;
                // ix = px * (W-1)/W, iy = py * (H-1)/H (H == W == 96)
                const float ix = px * (95.0f/96.0f);
                const float iy = py * (95.0f/96.0f);
                const float fx = floorf(ix), fy = floorf(iy);
                const float wx1 = ix - fx, wy1 = iy - fy;
                const float wx0 = 1.0f - wx1, wy0 = 1.0f - wy1;
                const int x0 = (int)fx, y0 = (int)fy;
                const bool vx0 = (unsigned)x0       < (unsigned)HMc;
                const bool vx1 = (unsigned)(x0 + 1) < (unsigned)HMc;
                const bool vy0 = (unsigned)y0       < (unsigned)HMc;
                const bool vy1 = (unsigned)(y0 + 1) < (unsigned)HMc;
                const float w00 = (vy0 && vx0) ? wy0*wx0 : 0.0f;
                const float w01 = (vy0 && vx1) ? wy0*wx1 : 0.0f;
                const float w10 = (vy1 && vx0) ? wy1*wx0 : 0.0f;
                const float w11 = (vy1 && vx1) ? wy1*wx1 : 0.0f;
                const float4* plane = hb + (size_t)v * (HMc*HMc*(Jc/4));
                corner_acc(plane, y0,   x0,   w00, vol);
                corner_acc(plane, y0,   x0+1, w01, vol);
                corner_acc(plane, y0+1, x0,   w10, vol);
                corner_acc(plane, y0+1, x0+1, w11, vol);
            }
        }

        // exp (volume in [0, 4] -> no max-shift needed) and accumulate
        #pragma unroll
        for (int q = 0; q < 6; ++q) {
            float e;
            e = __expf(vol[q].x);
            acc[q*4+0].x += e; acc[q*4+0].y += e*cx; acc[q*4+0].z += e*cy; acc[q*4+0].w += e*cz;
            e = __expf(vol[q].y);
            acc[q*4+1].x += e; acc[q*4+1].y += e*cx; acc[q*4+1].z += e*cy; acc[q*4+1].w += e*cz;
            e = __expf(vol[q].z);
            acc[q*4+2].x += e; acc[q*4+2].y += e*cx; acc[q*4+2].z += e*cy; acc[q*4+2].w += e*cz;
            e = __expf(vol[q].w);
            acc[q*4+3].x += e; acc[q*4+3].y += e*cx; acc[q*4+3].z += e*cy; acc[q*4+3].w += e*cz;
        }
    }

    // warp reduction (deterministic), then cross-warp via smem
    const int lane = tid & 31;
    const int wrp  = tid >> 5;
    #pragma unroll
    for (int j = 0; j < Jc; ++j) {
        float4 a = acc[j];
        #pragma unroll
        for (int o = 16; o > 0; o >>= 1) {
            a.x += __shfl_xor_sync(0xffffffffu, a.x, o);
            a.y += __shfl_xor_sync(0xffffffffu, a.y, o);
            a.z += __shfl_xor_sync(0xffffffffu, a.z, o);
            a.w += __shfl_xor_sync(0xffffffffu, a.w, o);
        }
        if (lane == 0) s4[wrp][j] = a;
    }
    __syncthreads();
    if (tid < Jc) {
        float4 a = s4[0][tid], b2 = s4[1][tid], c2 = s4[2][tid], d2 = s4[3][tid];
        float4 r = make_float4(a.x + b2.x + c2.x + d2.x,
                               a.y + b2.y + c2.y + d2.y,
                               a.z + b2.z + c2.z + d2.z,
                               a.w + b2.w + c2.w + d2.w);
        g_partial[(b*NBLK + blockIdx.x)*Jc + tid] = r;
    }
}

// ---------------------------------------------------------------------------
// Kernel C: reduce per-block partials -> coordinates [B, J, 3]
// One block per (b, j).
// ---------------------------------------------------------------------------
__global__ void finalize_kernel(float* __restrict__ out) {
    const int bj = blockIdx.x;            // 0..47
    const int b  = bj / Jc;
    const int j  = bj % Jc;
    const int tid = threadIdx.x;          // 128

    float4 a = make_float4(0.f, 0.f, 0.f, 0.f);
    for (int blk = tid; blk < NBLK; blk += 128) {
        float4 p = g_partial[(b*NBLK + blk)*Jc + j];
        a.x += p.x; a.y += p.y; a.z += p.z; a.w += p.w;
    }
    #pragma unroll
    for (int o = 16; o > 0; o >>= 1) {
        a.x += __shfl_xor_sync(0xffffffffu, a.x, o);
        a.y += __shfl_xor_sync(0xffffffffu, a.y, o);
        a.z += __shfl_xor_sync(0xffffffffu, a.z, o);
        a.w += __shfl_xor_sync(0xffffffffu, a.w, o);
    }
    __shared__ float4 s[4];
    const int lane = tid & 31, wrp = tid >> 5;
    if (lane == 0) s[wrp] = a;
    __syncthreads();
    if (tid == 0) {
        float4 r = s[0];
        r.x += s[1].x + s[2].x + s[3].x;
        r.y += s[1].y + s[2].y + s[3].y;
        r.z += s[1].z + s[2].z + s[3].z;
        r.w += s[1].w + s[2].w + s[3].w;
        const float inv = 1.0f / r.x;
        out[bj*3 + 0] = r.y * inv;
        out[bj*3 + 1] = r.z * inv;
        out[bj*3 + 2] = r.w * inv;
    }
}

// ---------------------------------------------------------------------------
extern "C" void kernel_launch(void* const* d_in, const int* in_sizes, int n_in,
                              void* d_out, int out_size) {
    const float* heatmaps = (const float*)d_in[0];   // (2,4,24,96,96)
    const float* proj     = (const float*)d_in[1];   // (2,4,3,4)
    const float* coords   = (const float*)d_in[2];   // (2,48,48,48,3)
    float* out = (float*)d_out;                      // (2,24,3)

    transpose_kernel<<<Bc*Vc*HMc, dim3(32, Jc)>>>(heatmaps);
    dim3 grid(NBLK, Bc);
    main_kernel<<<grid, TPB>>>(proj, coords);
    finalize_kernel<<<Bc*Jc, 128>>>(out);
}